// round 7
// baseline (speedup 1.0000x reference)
#include <cuda_runtime.h>
#include <cstdint>

typedef unsigned long long ull;

#define Ee   130
#define HE   1040
#define TOK  64            // tokens per tile
#define WST  68            // weight smem row stride (16B-aligned)
#define XST  68            // x smem row stride
#define NH   4             // heads per config

__device__ __forceinline__ ull splat2(float v) {
    ull r;
    asm("mov.b64 %0, {%1, %1};" : "=l"(r) : "r"(__float_as_uint(v)));
    return r;
}
__device__ __forceinline__ void fma2(ull& acc, ull a, ull b) {
    asm("fma.rn.f32x2 %0, %1, %2, %0;" : "+l"(acc) : "l"(a), "l"(b));
}
__device__ __forceinline__ ull pack2(uint32_t lo, uint32_t hi) {
    return (ull)lo | ((ull)hi << 32);
}

// ---------------------------------------------------------------------------
// Single launch. cfg = blockIdx.x & 3: 0=q, 1=k, 2=v(h0-3), 3=v(h4-7).
// 256 thr: warp&3 = head, warp>>2 = token half. Double-buffered x tile,
// one barrier per tile; zero/partner stores issued before mainloop.
// ---------------------------------------------------------------------------
__global__ void __launch_bounds__(256, 2) fused_kernel(
    const float* __restrict__ x,
    const float* __restrict__ Mq, const float* __restrict__ Bq,
    const float* __restrict__ Mk, const float* __restrict__ Bk,
    const float* __restrict__ Mv,
    float* __restrict__ out, long S, int ntiles, int nbper)
{
    extern __shared__ float smem[];
    float* wsm = smem;                     // [NH][64 k][WST]
    float* xs0 = smem + NH * 64 * WST;     // [2][TOK][XST]

    const int cfg  = blockIdx.x & 3;
    const int bset = blockIdx.x >> 2;

    const float* M;  const float* Bv = Bq;
    float* ob;  int x_off, mode, ho;
    if (cfg == 0)      { M = Mq;             ob = out;         x_off = 65; mode = 0; ho = 0; Bv = Bq; }
    else if (cfg == 1) { M = Mk;             ob = out + S;     x_off = 0;  mode = 1; ho = 0; Bv = Bk; }
    else if (cfg == 2) { M = Mv;             ob = out + 2 * S; x_off = 0;  mode = 2; ho = 0; }
    else               { M = Mv + (4 << 12); ob = out + 2 * S; x_off = 0;  mode = 2; ho = 4; }

    const int tid = threadIdx.x;

    // weights transposed: wsm[h][j][i] = M[h][i][j]; coalesced LDG
    for (int idx = tid; idx < (NH << 12); idx += 256) {
        int h = idx >> 12, rem = idx & 4095, i = rem >> 6, j = rem & 63;
        wsm[h * (64 * WST) + j * WST + i] = M[idx];
    }

    const int warp = tid >> 5, lane = tid & 31;
    const int hw_i = warp & 3, half = warp >> 2;
    const int colg = lane & 7, g = lane >> 3;
    const int head = ho + hw_i;
    const int toff = half << 5;
    const float* hw = wsm + hw_i * (64 * WST);
    const float  bmain = (mode == 2) ? 0.f : Bv[head];
    const float  bpart = (mode == 2) ? 0.f : Bv[head + 4];
    const int    sidx  = (mode == 1) ? 64 : 65;
    const bool   evenh = !(head & 1);
    const ulonglong2 zz = make_ulonglong2(0ULL, 0ULL);
    const float4 zf = make_float4(0.f, 0.f, 0.f, 0.f);

    // prologue: fill buffer 0 with first tile
    {
        const float* xg = x + (long)bset * TOK * Ee;
#pragma unroll 4
        for (int idx = tid; idx < TOK * 66; idx += 256) {
            int t = idx / 66, c = idx - t * 66;
            int src = (c < 64) ? (x_off + c) : ((c == 64) ? 64 : 129);
            xs0[t * XST + c] = xg[t * Ee + src];
        }
    }

    int buf = 0;
    for (int tile = bset; tile < ntiles; tile += nbper) {
        __syncthreads();                           // xs[buf] filled; prev reads of xs[buf^1] done
        float* xs_b = xs0 + buf * (TOK * XST);
        const long tok0 = (long)tile * TOK;

        // fill next tile into other buffer (LDG latency overlaps everything below)
        int ntile = tile + nbper;
        if (ntile < ntiles) {
            float* xs_n = xs0 + (buf ^ 1) * (TOK * XST);
            const float* xg = x + (long)ntile * TOK * Ee;
#pragma unroll 4
            for (int idx = tid; idx < TOK * 66; idx += 256) {
                int t = idx / 66, c = idx - t * 66;
                int src = (c < 64) ? (x_off + c) : ((c == 64) ? 64 : 129);
                xs_n[t * XST + c] = xg[t * Ee + src];
            }
        }

        float* r0 = ob + tok0 * HE + head * Ee;    // main row base; row t = r0 + t*HE
        float* r4 = r0 + 4 * Ee;                   // partner row base

        // ---- zero cols 0..63 of this warp's 32 main rows (acc-independent)
        if (evenh) {
            for (int it = lane; it < 512; it += 32) {
                int t = toff + (it >> 4), j = it & 15;
                ((ulonglong2*)(r0 + (long)t * HE))[j] = zz;
            }
        } else {
            for (int it = lane; it < 512; it += 32) {
                int t = toff + (it >> 4), j = it & 15;
                float* rp = r0 + (long)t * HE;
                if (j == 0) { *(ull*)rp = 0ULL; *(ull*)(rp + 62) = 0ULL; }
                else        *(float4*)(rp + 4 * j - 2) = zf;
            }
        }
        // ---- partner rows (q/k): zero except col 65 = s * bpart
        if (mode < 2) {
            if (evenh) {
                for (int it = lane; it < 32 * 33; it += 32) {
                    int tl = it / 33, j = it - tl * 33, t = toff + tl;
                    float* rp = r4 + (long)t * HE;
                    if (j == 32)      *(ull*)(rp + 128) = 0ULL;
                    else if (j == 16) {
                        float sv = xs_b[t * XST + sidx] * bpart;
                        *(float4*)(rp + 64) = make_float4(0.f, sv, 0.f, 0.f);
                    } else            *(float4*)(rp + 4 * j) = zf;
                }
            } else {
                for (int it = lane; it < 32 * 34; it += 32) {
                    int tl = it / 34, j = it - tl * 34, t = toff + tl;
                    float* rp = r4 + (long)t * HE;
                    if (j == 0)       *(ull*)rp = 0ULL;
                    else if (j == 33) *(ull*)(rp + 128) = 0ULL;
                    else if (j == 32) *(ull*)(rp + 126) = 0ULL;
                    else if (j == 16) {
                        float sv = xs_b[t * XST + sidx] * bpart;
                        *(float4*)(rp + 62) = make_float4(0.f, 0.f, 0.f, sv);
                    } else            *(float4*)(rp + 4 * j - 2) = zf;
                }
            }
        }

        // ---- mainloop: 8 tokens x 8 cols per lane, f32x2 FMA
        ull acc[8][4];
#pragma unroll
        for (int i = 0; i < 8; i++)
#pragma unroll
            for (int c = 0; c < 4; c++) acc[i][c] = 0ULL;

        const float* xsw = xs_b + (toff + g) * XST;
#pragma unroll 2
        for (int kc = 0; kc < 16; kc++) {
            ull w[16];
            const float* wp = hw + kc * 4 * WST + colg * 8;
#pragma unroll
            for (int kk = 0; kk < 4; kk++) {
                ulonglong2 wa = *(const ulonglong2*)(wp + kk * WST);
                ulonglong2 wb = *(const ulonglong2*)(wp + kk * WST + 4);
                w[kk * 4 + 0] = wa.x; w[kk * 4 + 1] = wa.y;
                w[kk * 4 + 2] = wb.x; w[kk * 4 + 3] = wb.y;
            }
#pragma unroll
            for (int i = 0; i < 8; i++) {
                const float4 xv = *(const float4*)(xsw + i * 4 * XST + kc * 4);
                float xa[4] = {xv.x, xv.y, xv.z, xv.w};
#pragma unroll
                for (int kk = 0; kk < 4; kk++) {
                    ull xx = splat2(xa[kk]);
#pragma unroll
                    for (int c = 0; c < 4; c++) fma2(acc[i][c], w[kk * 4 + c], xx);
                }
            }
        }

        // ---- main-row result stores (cols 64..129), parity-vectorized
#pragma unroll
        for (int i = 0; i < 8; i++) {
            const int t = toff + i * 4 + g;
            float myhi = __uint_as_float((uint32_t)(acc[i][3] >> 32));
            float prev = __shfl_up_sync(0xffffffffu, myhi, 1);
            if (colg == 0) prev = 0.f;
            ull v0 = pack2(__float_as_uint(prev), (uint32_t)acc[i][0]);
            ull v1 = pack2((uint32_t)(acc[i][0] >> 32), (uint32_t)acc[i][1]);
            ull v2 = pack2((uint32_t)(acc[i][1] >> 32), (uint32_t)acc[i][2]);
            ull v3 = pack2((uint32_t)(acc[i][2] >> 32), (uint32_t)acc[i][3]);
            ull* op = (ull*)(r0 + (long)t * HE + 64 + colg * 8);
            if (evenh) {
                ((ulonglong2*)op)[0] = make_ulonglong2(v0, v1);
                ((ulonglong2*)op)[1] = make_ulonglong2(v2, v3);
            } else {
                op[0] = v0;
                *(ulonglong2*)(op + 1) = make_ulonglong2(v1, v2);
                op[3] = v3;
            }
            if (colg == 7) {
                float b = bmain * xs_b[t * XST + 65];
                op[4] = pack2((uint32_t)(acc[i][3] >> 32), __float_as_uint(b));
            }
        }
        buf ^= 1;
    }
}

extern "C" void kernel_launch(void* const* d_in, const int* in_sizes, int n_in,
                              void* d_out, int out_size)
{
    const float* x  = (const float*)d_in[0];
    const float* Mq = (const float*)d_in[1];
    const float* Bq = (const float*)d_in[2];
    const float* Mk = (const float*)d_in[3];
    const float* Bk = (const float*)d_in[4];
    const float* Mv = (const float*)d_in[5];
    float* out = (float*)d_out;

    const int ntok   = in_sizes[0] / Ee;            // 32768
    const int ntiles = (ntok + TOK - 1) / TOK;      // 512
    const long S     = (long)out_size / 3;

    const int grid  = 296;
    const int nbper = grid / 4;
    const int smem  = (NH * 64 * WST + 2 * TOK * XST) * (int)sizeof(float); // 104,448 B
    cudaFuncSetAttribute(fused_kernel, cudaFuncAttributeMaxDynamicSharedMemorySize, smem);

    fused_kernel<<<grid, 256, smem>>>(x, Mq, Bq, Mk, Bk, Mv, out, S, ntiles, nbper);
}

// round 9
// speedup vs baseline: 1.3303x; 1.3303x over previous
#include <cuda_runtime.h>
#include <cstdint>

typedef unsigned long long ull;

#define Ee   130
#define HE   1040
#define TOK  32            // tokens per tile
#define WST  64            // weight smem row stride (no pad needed now)
#define XST  68            // x smem row stride
#define NH   4             // heads per config

__device__ __forceinline__ ull splat2(float v) {
    ull r;
    asm("mov.b64 %0, {%1, %1};" : "=l"(r) : "r"(__float_as_uint(v)));
    return r;
}
__device__ __forceinline__ void fma2(ull& acc, ull a, ull b) {
    asm("fma.rn.f32x2 %0, %1, %2, %0;" : "+l"(acc) : "l"(a), "l"(b));
}
__device__ __forceinline__ ull pack2(uint32_t lo, uint32_t hi) {
    return (ull)lo | ((ull)hi << 32);
}

// ---------------------------------------------------------------------------
// Single launch, grid 444 (one wave @ 3 CTAs/SM). cfg = blockIdx.x & 3:
// 0=q, 1=k, 2=v(h0-3), 3=v(h4-7). 256 thr: warp&3 = head, warp>>2 = 16-token
// half of the 32-token tile. Lane: g = lane>>3 owns tokens {g,4+g,8+g,12+g};
// colg = lane&7 owns column PAIRS j = 2*colg + 16*c (c=0..3) -> weight LDS
// hits banks {2colg, 2colg+1}: conflict-free.
// ---------------------------------------------------------------------------
__global__ void __launch_bounds__(256, 3) fused_kernel(
    const float* __restrict__ x,
    const float* __restrict__ Mq, const float* __restrict__ Bq,
    const float* __restrict__ Mk, const float* __restrict__ Bk,
    const float* __restrict__ Mv,
    float* __restrict__ out, long S, int ntiles, int nbper)
{
    extern __shared__ float smem[];
    float* wsm = smem;                   // [NH][64 j][64 i]  (transposed)
    float* xs  = smem + NH * 64 * WST;   // [TOK][XST]: 0..63 slice, 64 s_mid, 65 s_last

    const int cfg  = blockIdx.x & 3;
    const int bset = blockIdx.x >> 2;

    const float* M;  const float* Bv = Bq;
    float* ob;  int x_off, mode, ho;
    if (cfg == 0)      { M = Mq;             ob = out;         x_off = 65; mode = 0; ho = 0; Bv = Bq; }
    else if (cfg == 1) { M = Mk;             ob = out + S;     x_off = 0;  mode = 1; ho = 0; Bv = Bk; }
    else if (cfg == 2) { M = Mv;             ob = out + 2 * S; x_off = 0;  mode = 2; ho = 0; }
    else               { M = Mv + (4 << 12); ob = out + 2 * S; x_off = 0;  mode = 2; ho = 4; }

    const int tid = threadIdx.x;

    // weights transposed: wsm[h][j][i] = M[h][i][j]  (y_i = sum_j M[i][j] x[j])
    for (int idx = tid; idx < (NH << 12); idx += 256) {
        int h = idx >> 12, rem = idx & 4095, i = rem >> 6, j = rem & 63;
        wsm[h * 4096 + j * WST + i] = M[idx];
    }

    const int warp = tid >> 5, lane = tid & 31;
    const int hw_i = warp & 3, half = warp >> 2;
    const int colg = lane & 7, g = lane >> 3;
    const int head = ho + hw_i;
    const int toff = half << 4;          // 0 or 16
    const float* hw = wsm + hw_i * 4096;
    const float  bmain = (mode == 2) ? 0.f : Bv[head];
    const float  bpart = (mode == 2) ? 0.f : Bv[head + 4];
    const int    sidx  = (mode == 1) ? 64 : 65;

    for (int tile = bset; tile < ntiles; tile += nbper) {
        const long tok0 = (long)tile * TOK;
        __syncthreads();                 // protect xs from previous iteration
        const float* xg = x + tok0 * Ee;
        for (int idx = tid; idx < TOK * 66; idx += 256) {
            int t = idx / 66, c = idx - t * 66;
            int src = (c < 64) ? (x_off + c) : ((c == 64) ? 64 : 129);
            xs[t * XST + c] = xg[t * Ee + src];
        }
        __syncthreads();

        // ---- mainloop: 4 tokens x 4 col-pairs per lane
        ull acc[4][4];
#pragma unroll
        for (int i = 0; i < 4; i++)
#pragma unroll
            for (int c = 0; c < 4; c++) acc[i][c] = 0ULL;

        const float* xsw   = xs + (toff + g) * XST;
        const float* wbase = hw + 2 * colg;
#pragma unroll 1
        for (int kc = 0; kc < 16; kc++) {
            float4 xv[4];
#pragma unroll
            for (int i = 0; i < 4; i++)
                xv[i] = *(const float4*)(xsw + i * 4 * XST + kc * 4);
#pragma unroll
            for (int kk = 0; kk < 4; kk++) {
                const float* wk = wbase + (kc * 4 + kk) * WST;
                ull w0 = *(const ull*)(wk);
                ull w1 = *(const ull*)(wk + 16);
                ull w2 = *(const ull*)(wk + 32);
                ull w3 = *(const ull*)(wk + 48);
#pragma unroll
                for (int i = 0; i < 4; i++) {
                    float xk = (kk == 0) ? xv[i].x : (kk == 1) ? xv[i].y
                             : (kk == 2) ? xv[i].z : xv[i].w;
                    ull xx = splat2(xk);
                    fma2(acc[i][0], w0, xx);
                    fma2(acc[i][1], w1, xx);
                    fma2(acc[i][2], w2, xx);
                    fma2(acc[i][3], w3, xx);
                }
            }
        }

        // ---- main-row result stores (cols 64..129)
        // row[64+2colg+16c .. +1] = (y[2colg+16c-1], y[2colg+16c])
#pragma unroll
        for (int i = 0; i < 4; i++) {
            const int t = toff + i * 4 + g;
            float* rp = ob + (tok0 + t) * HE + head * Ee;
            float hic[4], pu[4], pb[4];
#pragma unroll
            for (int c = 0; c < 4; c++) {
                hic[c] = __uint_as_float((uint32_t)(acc[i][c] >> 32));
                pu[c]  = __shfl_up_sync(0xffffffffu, hic[c], 1);
            }
#pragma unroll
            for (int c = 1; c < 4; c++)
                pb[c] = __shfl_sync(0xffffffffu, hic[c - 1], 7, 8);
#pragma unroll
            for (int c = 0; c < 4; c++) {
                float prev = colg ? pu[c] : (c ? pb[c] : 0.f);
                *(ull*)(rp + 64 + 2 * colg + 16 * c) =
                    pack2(__float_as_uint(prev), (uint32_t)acc[i][c]);
            }
            if (colg == 7) {
                float b = bmain * xs[t * XST + 65];   // s_last * B[h] (0 for v)
                *(ull*)(rp + 128) = pack2((uint32_t)(acc[i][3] >> 32), __float_as_uint(b));
            }
        }

        // ---- zero cols 0..63 of this warp's 16 main rows
        for (int idx = lane; idx < 16 * 32; idx += 32) {
            int t = toff + (idx >> 5), m = idx & 31;
            ((ull*)(ob + (tok0 + t) * HE + head * Ee))[m] = 0ULL;
        }
        // ---- partner rows (q/k only): zero except col 65 = s * bpart
        if (mode < 2) {
            for (int idx = lane; idx < 16 * 65; idx += 32) {
                int t = toff + idx / 65, m = idx % 65;
                ull v = 0ULL;
                if (m == 32) {
                    float s = xs[t * XST + sidx];
                    v = (ull)__float_as_uint(s * bpart) << 32;  // (col64=0, col65=s*b)
                }
                ((ull*)(ob + (tok0 + t) * HE + (head + 4) * Ee))[m] = v;
            }
        }
    }
}

extern "C" void kernel_launch(void* const* d_in, const int* in_sizes, int n_in,
                              void* d_out, int out_size)
{
    const float* x  = (const float*)d_in[0];
    const float* Mq = (const float*)d_in[1];
    const float* Bq = (const float*)d_in[2];
    const float* Mk = (const float*)d_in[3];
    const float* Bk = (const float*)d_in[4];
    const float* Mv = (const float*)d_in[5];
    float* out = (float*)d_out;

    const int ntok   = in_sizes[0] / Ee;            // 32768
    const int ntiles = (ntok + TOK - 1) / TOK;      // 1024
    const long S     = (long)out_size / 3;

    const int grid  = 444;                          // 111 blocks per config; 1 wave @ 3 CTA/SM
    const int nbper = grid / 4;
    const int smem  = (NH * 64 * WST + TOK * XST) * (int)sizeof(float); // 74,240 B
    cudaFuncSetAttribute(fused_kernel, cudaFuncAttributeMaxDynamicSharedMemorySize, smem);

    fused_kernel<<<grid, 256, smem>>>(x, Mq, Bq, Mk, Bk, Mv, out, S, ntiles, nbper);
}

// round 10
// speedup vs baseline: 1.3343x; 1.0030x over previous
#include <cuda_runtime.h>
#include <cstdint>

typedef unsigned long long ull;

#define Ee   130
#define HE   1040
#define TOK  32            // tokens per tile
#define WST  64            // weight smem row stride
#define XST  68            // x smem row stride
#define NH   4             // heads per config

__device__ __forceinline__ ull splat2(float v) {
    ull r;
    asm("mov.b64 %0, {%1, %1};" : "=l"(r) : "r"(__float_as_uint(v)));
    return r;
}
__device__ __forceinline__ void fma2(ull& acc, ull a, ull b) {
    asm("fma.rn.f32x2 %0, %1, %2, %0;" : "+l"(acc) : "l"(a), "l"(b));
}
__device__ __forceinline__ ull pack2(uint32_t lo, uint32_t hi) {
    return (ull)lo | ((ull)hi << 32);
}
__device__ __forceinline__ uint32_t hi32(ull v) { return (uint32_t)(v >> 32); }

// ---------------------------------------------------------------------------
// Single launch, grid 444 (one wave @ 3 CTAs/SM). cfg = blockIdx.x & 3:
// 0=q, 1=k, 2=v(h0-3), 3=v(h4-7). 256 thr: warp&3 = head, warp>>2 = 16-token
// half. Lane: g = lane>>3 owns tokens {g,4+g,8+g,12+g}; colg = lane&7 owns
// column QUADS j = 4*colg + 32*c (c=0,1) -> weight loads are 2x LDS.128,
// conflict-free (128B contiguous per 8-lane phase, 4-way g-broadcast).
// ---------------------------------------------------------------------------
__global__ void __launch_bounds__(256, 3) fused_kernel(
    const float* __restrict__ x,
    const float* __restrict__ Mq, const float* __restrict__ Bq,
    const float* __restrict__ Mk, const float* __restrict__ Bk,
    const float* __restrict__ Mv,
    float* __restrict__ out, long S, int ntiles, int nbper)
{
    extern __shared__ float smem[];
    float* wsm = smem;                   // [NH][64 j][64 i]  (transposed)
    float* xs  = smem + NH * 64 * WST;   // [TOK][XST]: 0..63 slice, 64 s_mid, 65 s_last

    const int cfg  = blockIdx.x & 3;
    const int bset = blockIdx.x >> 2;

    const float* M;  const float* Bv = Bq;
    float* ob;  int x_off, mode, ho;
    if (cfg == 0)      { M = Mq;             ob = out;         x_off = 65; mode = 0; ho = 0; Bv = Bq; }
    else if (cfg == 1) { M = Mk;             ob = out + S;     x_off = 0;  mode = 1; ho = 0; Bv = Bk; }
    else if (cfg == 2) { M = Mv;             ob = out + 2 * S; x_off = 0;  mode = 2; ho = 0; }
    else               { M = Mv + (4 << 12); ob = out + 2 * S; x_off = 0;  mode = 2; ho = 4; }

    const int tid = threadIdx.x;

    // weights transposed: wsm[h][j][i] = M[h][i][j]
    for (int idx = tid; idx < (NH << 12); idx += 256) {
        int h = idx >> 12, rem = idx & 4095, i = rem >> 6, j = rem & 63;
        wsm[h * 4096 + j * WST + i] = M[idx];
    }

    const int warp = tid >> 5, lane = tid & 31;
    const int hw_i = warp & 3, half = warp >> 2;
    const int colg = lane & 7, g = lane >> 3;
    const int head = ho + hw_i;
    const int toff = half << 4;          // 0 or 16
    const float* hw = wsm + hw_i * 4096;
    const float  bmain = (mode == 2) ? 0.f : Bv[head];
    const float  bpart = (mode == 2) ? 0.f : Bv[head + 4];
    const int    sidx  = (mode == 1) ? 64 : 65;
    const bool   evenh = !(head & 1);    // row base 16B-aligned iff head even
    const float4 zf = make_float4(0.f, 0.f, 0.f, 0.f);

    for (int tile = bset; tile < ntiles; tile += nbper) {
        const long tok0 = (long)tile * TOK;
        __syncthreads();
        const float* xg = x + tok0 * Ee;
        for (int idx = tid; idx < TOK * 66; idx += 256) {
            int t = idx / 66, c = idx - t * 66;
            int src = (c < 64) ? (x_off + c) : ((c == 64) ? 64 : 129);
            xs[t * XST + c] = xg[t * Ee + src];
        }
        __syncthreads();

        // ---- mainloop: 4 tokens x 2 col-quads per lane
        // acc[i]: 0=(yC,yC+1) 1=(yC+2,yC+3) 2=(y32+C,y33+C) 3=(y34+C,y35+C), C=4colg
        ull acc[4][4];
#pragma unroll
        for (int i = 0; i < 4; i++)
#pragma unroll
            for (int c = 0; c < 4; c++) acc[i][c] = 0ULL;

        const float* xsw   = xs + (toff + g) * XST;
        const float* wbase = hw + 4 * colg;
#pragma unroll 1
        for (int kc = 0; kc < 16; kc++) {
            float4 xv[4];
#pragma unroll
            for (int i = 0; i < 4; i++)
                xv[i] = *(const float4*)(xsw + i * 4 * XST + kc * 4);
#pragma unroll
            for (int kk = 0; kk < 4; kk++) {
                const float* wk = wbase + (kc * 4 + kk) * WST;
                ulonglong2 wa = *(const ulonglong2*)(wk);        // y[C..C+3]
                ulonglong2 wb = *(const ulonglong2*)(wk + 32);   // y[32+C..35+C]
#pragma unroll
                for (int i = 0; i < 4; i++) {
                    float xk = (kk == 0) ? xv[i].x : (kk == 1) ? xv[i].y
                             : (kk == 2) ? xv[i].z : xv[i].w;
                    ull xx = splat2(xk);
                    fma2(acc[i][0], wa.x, xx);
                    fma2(acc[i][1], wa.y, xx);
                    fma2(acc[i][2], wb.x, xx);
                    fma2(acc[i][3], wb.y, xx);
                }
            }
        }

        // ---- main-row result stores (cols 64..129)
#pragma unroll
        for (int i = 0; i < 4; i++) {
            const int t = toff + i * 4 + g;
            float* rp = ob + (tok0 + t) * HE + head * Ee;
            float h1 = __uint_as_float(hi32(acc[i][1]));   // y[C+3]
            float h3 = __uint_as_float(hi32(acc[i][3]));   // y[35+C]
            float pu0 = __shfl_up_sync(0xffffffffu, h1, 1);    // y[C-1]
            float pu1 = __shfl_up_sync(0xffffffffu, h3, 1);    // y[31+C]
            float pb  = __shfl_sync(0xffffffffu, h1, 7, 8);    // y[31] (for colg=0)
            float prev0 = colg ? pu0 : 0.f;                    // col64 = 0
            float prev1 = colg ? pu1 : pb;
            const int C = 4 * colg;
            *(ull*)(rp + 64 + C)      = pack2(__float_as_uint(prev0), (uint32_t)acc[i][0]);
            *(ull*)(rp + 66 + C)      = pack2(hi32(acc[i][0]), (uint32_t)acc[i][1]);
            *(ull*)(rp + 96 + C)      = pack2(__float_as_uint(prev1), (uint32_t)acc[i][2]);
            *(ull*)(rp + 98 + C)      = pack2(hi32(acc[i][2]), (uint32_t)acc[i][3]);
            if (colg == 7) {
                float b = bmain * xs[t * XST + 65];   // s_last * B[h] (0 for v)
                *(ull*)(rp + 128) = pack2(hi32(acc[i][3]), __float_as_uint(b));
            }
        }

        // ---- zero cols 0..63 of this warp's 16 main rows (parity-vectorized)
        float* rb0 = ob + (tok0 + toff) * HE + head * Ee;
        if (evenh) {
            for (int idx = lane; idx < 256; idx += 32) {
                int t = idx >> 4, j = idx & 15;
                *(float4*)(rb0 + (long)t * HE + 4 * j) = zf;
            }
        } else {
            for (int idx = lane; idx < 256; idx += 32) {
                int t = idx >> 4, j = idx & 15;
                float* rp = rb0 + (long)t * HE;
                if (j == 0) { *(ull*)rp = 0ULL; *(ull*)(rp + 62) = 0ULL; }
                else        *(float4*)(rp + 4 * j - 2) = zf;
            }
        }
        // ---- partner rows (q/k only): zero except col 65 = s * bpart
        if (mode < 2) {
            float* rb4 = rb0 + 4 * Ee;
            if (evenh) {
                for (int idx = lane; idx < 512; idx += 32) {
                    int t = idx >> 5, j = idx & 31;
                    float4 v = zf;
                    if (j == 16) v.y = xs[(toff + t) * XST + sidx] * bpart;  // col 65
                    *(float4*)(rb4 + (long)t * HE + 4 * j) = v;
                }
                if (lane < 16) *(ull*)(rb4 + (long)lane * HE + 128) = 0ULL;
            } else {
                for (int idx = lane; idx < 512; idx += 32) {
                    int t = idx >> 5, j = idx & 31;
                    float* rp = rb4 + (long)t * HE;
                    if (j == 0) { *(ull*)rp = 0ULL; *(ull*)(rp + 126) = 0ULL; }
                    else {
                        float4 v = zf;
                        if (j == 16) v.w = xs[(toff + t) * XST + sidx] * bpart; // col 65
                        *(float4*)(rp + 4 * j - 2) = v;
                    }
                }
                if (lane < 16) *(ull*)(rb4 + (long)lane * HE + 128) = 0ULL;
            }
        }
    }
}

extern "C" void kernel_launch(void* const* d_in, const int* in_sizes, int n_in,
                              void* d_out, int out_size)
{
    const float* x  = (const float*)d_in[0];
    const float* Mq = (const float*)d_in[1];
    const float* Bq = (const float*)d_in[2];
    const float* Mk = (const float*)d_in[3];
    const float* Bk = (const float*)d_in[4];
    const float* Mv = (const float*)d_in[5];
    float* out = (float*)d_out;

    const int ntok   = in_sizes[0] / Ee;            // 32768
    const int ntiles = (ntok + TOK - 1) / TOK;      // 1024
    const long S     = (long)out_size / 3;

    const int grid  = 444;                          // 111 blocks per config
    const int nbper = grid / 4;
    const int smem  = (NH * 64 * WST + TOK * XST) * (int)sizeof(float); // 74,240 B
    cudaFuncSetAttribute(fused_kernel, cudaFuncAttributeMaxDynamicSharedMemorySize, smem);

    fused_kernel<<<grid, 256, smem>>>(x, Mq, Bq, Mk, Bk, Mv, out, S, ntiles, nbper);
}